// round 6
// baseline (speedup 1.0000x reference)
#include <cuda_runtime.h>
#include <math.h>

#define NN 32768     // total nodes
#define NE 524288    // total edges
#define H 64         // hidden
#define H2 128       // 2*hidden
#define NBATCH 16
#define NS 2048      // nodes per graph
#define NL 4
#define NY 64
#define TE 64        // rows per GEMM tile
#define TEP 68       // padded tile stride
#define EPSN 1e-5f
#define GRID_MLP 296

typedef unsigned long long u64;

__device__ float g_h[NN * H];
__device__ float g_agg[NN * H];
__device__ float g_u[NN * H];
__device__ float g_stats[NBATCH * H * 2];
__device__ float g_X[NN * 3];
__device__ float g_Y[NY * 3];
__device__ double g_acc[3];

// ---- packed fp32x2 helpers (sm_100+ FFMA2) ----
__device__ __forceinline__ u64 fma2(u64 a, u64 b, u64 c) {
    u64 d;
    asm("fma.rn.f32x2 %0, %1, %2, %3;" : "=l"(d) : "l"(a), "l"(b), "l"(c));
    return d;
}
__device__ __forceinline__ u64 dup2(float w) {
    u64 d;
    asm("mov.b64 %0, {%1, %1};" : "=l"(d) : "f"(w));
    return d;
}
__device__ __forceinline__ float2 unpack2(u64 u) {
    float2 f;
    asm("mov.b64 {%0, %1}, %2;" : "=f"(f.x), "=f"(f.y) : "l"(u));
    return f;
}

// -------------------- encoder: h = x @ enc_W + enc_b --------------------
__global__ void k_encode(const float* __restrict__ x, const float* __restrict__ W,
                         const float* __restrict__ b) {
    int idx = blockIdx.x * blockDim.x + threadIdx.x;
    int n = idx >> 6, c = idx & 63;
    float x0 = x[n * 3 + 0], x1 = x[n * 3 + 1], x2 = x[n * 3 + 2];
    g_h[idx] = fmaf(x0, W[c], fmaf(x1, W[H + c], fmaf(x2, W[2 * H + c], b[c])));
}

// -------------------- fused 2-layer MLP, persistent tile loop --------------------
// MODE 0: edge MLP, rows = [h[dst]; h[src]], epilogue scatter-add to g_agg.
// MODE 1: node MLP, rows = [h[n]; agg[n]], epilogue store g_u + IN stats.
template <int MODE>
__global__ void __launch_bounds__(256, 2)
k_mlp(const int* __restrict__ esrc, const int* __restrict__ edst,
      const float* __restrict__ W1, const float* __restrict__ b1,
      const float* __restrict__ W2, const float* __restrict__ b2) {
    extern __shared__ float sm[];
    float* sW1 = sm;                  // [128][64]
    float* sW2 = sW1 + H2 * H;        // [64][64]
    float* sA  = sW2 + H * H;         // [128][TEP]  input, transposed (k-major)
    float* sT  = sA + H2 * TEP;       // [64][TEP]   hidden, transposed
    int*   sDst = (int*)(sT + H * TEP);

    const int tid = threadIdx.x;
    const int tx = tid & 15, ty = tid >> 4;

    {   // stage weights once per block
        const float4* g1 = (const float4*)W1;
        float4* d1 = (float4*)sW1;
#pragma unroll
        for (int t = 0; t < 8; ++t) d1[tid + t * 256] = g1[tid + t * 256];
        const float4* g2 = (const float4*)W2;
        float4* d2 = (float4*)sW2;
#pragma unroll
        for (int t = 0; t < 4; ++t) d2[tid + t * 256] = g2[tid + t * 256];
    }
    float bia1[4], bia2[4];
#pragma unroll
    for (int j = 0; j < 4; j++) { bia1[j] = b1[tx * 4 + j]; bia2[j] = b2[tx * 4 + j]; }

    const int ntiles = (MODE == 0) ? (NE / TE) : (NN / TE);

    for (int tile = blockIdx.x; tile < ntiles; tile += gridDim.x) {
        const int e0 = tile * TE;
        __syncthreads();   // protect smem reuse across iterations / weight staging

        if (MODE == 0 && tid < TE) sDst[tid] = edst[e0 + tid];

        {   // gather: 4 threads per row, transposed store
            int e = tid >> 2, p = tid & 3;
            const float4 *r0, *r1;
            if (MODE == 0) {
                int rd = edst[e0 + e], rs = esrc[e0 + e];
                r0 = (const float4*)(g_h + rd * H);
                r1 = (const float4*)(g_h + rs * H);
            } else {
                int n = e0 + e;
                r0 = (const float4*)(g_h + n * H);
                r1 = (const float4*)(g_agg + n * H);
            }
#pragma unroll
            for (int q = 0; q < 4; ++q) {
                float4 v = r0[p * 4 + q];
                int k = p * 16 + q * 4;
                sA[(k + 0) * TEP + e] = v.x; sA[(k + 1) * TEP + e] = v.y;
                sA[(k + 2) * TEP + e] = v.z; sA[(k + 3) * TEP + e] = v.w;
                float4 w = r1[p * 4 + q];
                sA[(k + 64) * TEP + e] = w.x; sA[(k + 65) * TEP + e] = w.y;
                sA[(k + 66) * TEP + e] = w.z; sA[(k + 67) * TEP + e] = w.w;
            }
        }
        __syncthreads();

        // ---- GEMM1: [TE,128] x [128,64], packed rows ----
        u64 acc[2][4];
#pragma unroll
        for (int p = 0; p < 2; p++)
#pragma unroll
            for (int j = 0; j < 4; j++) acc[p][j] = 0ull;

#pragma unroll 8
        for (int k = 0; k < H2; ++k) {
            const u64* ap = (const u64*)(sA + k * TEP + ty * 4);
            u64 a01 = ap[0], a23 = ap[1];
            float4 w4 = *(const float4*)(sW1 + k * H + tx * 4);
            u64 w0 = dup2(w4.x), w1 = dup2(w4.y), w2 = dup2(w4.z), w3 = dup2(w4.w);
            acc[0][0] = fma2(a01, w0, acc[0][0]); acc[1][0] = fma2(a23, w0, acc[1][0]);
            acc[0][1] = fma2(a01, w1, acc[0][1]); acc[1][1] = fma2(a23, w1, acc[1][1]);
            acc[0][2] = fma2(a01, w2, acc[0][2]); acc[1][2] = fma2(a23, w2, acc[1][2]);
            acc[0][3] = fma2(a01, w3, acc[0][3]); acc[1][3] = fma2(a23, w3, acc[1][3]);
        }
        // bias + relu -> sT (transposed)
#pragma unroll
        for (int j = 0; j < 4; j++) {
            float bb = bia1[j];
            float2 f0 = unpack2(acc[0][j]);
            float2 f1 = unpack2(acc[1][j]);
            float* dst = sT + (tx * 4 + j) * TEP + ty * 4;
            *(float2*)(dst)     = make_float2(fmaxf(f0.x + bb, 0.f), fmaxf(f0.y + bb, 0.f));
            *(float2*)(dst + 2) = make_float2(fmaxf(f1.x + bb, 0.f), fmaxf(f1.y + bb, 0.f));
        }
        __syncthreads();

        // ---- GEMM2: [TE,64] x [64,64], packed rows ----
        u64 acc2[2][4];
#pragma unroll
        for (int p = 0; p < 2; p++)
#pragma unroll
            for (int j = 0; j < 4; j++) acc2[p][j] = 0ull;

#pragma unroll 8
        for (int k = 0; k < H; ++k) {
            const u64* ap = (const u64*)(sT + k * TEP + ty * 4);
            u64 a01 = ap[0], a23 = ap[1];
            float4 w4 = *(const float4*)(sW2 + k * H + tx * 4);
            u64 w0 = dup2(w4.x), w1 = dup2(w4.y), w2 = dup2(w4.z), w3 = dup2(w4.w);
            acc2[0][0] = fma2(a01, w0, acc2[0][0]); acc2[1][0] = fma2(a23, w0, acc2[1][0]);
            acc2[0][1] = fma2(a01, w1, acc2[0][1]); acc2[1][1] = fma2(a23, w1, acc2[1][1]);
            acc2[0][2] = fma2(a01, w2, acc2[0][2]); acc2[1][2] = fma2(a23, w2, acc2[1][2]);
            acc2[0][3] = fma2(a01, w3, acc2[0][3]); acc2[1][3] = fma2(a23, w3, acc2[1][3]);
        }

        // unpack: vout[i][j], i = local row (ty*4+i), j = col (tx*4+j)
        float vout[4][4];
#pragma unroll
        for (int p = 0; p < 2; p++)
#pragma unroll
            for (int j = 0; j < 4; j++) {
                float bb = bia2[j];
                float2 f = unpack2(acc2[p][j]);
                vout[2 * p + 0][j] = fmaxf(f.x + bb, 0.f);
                vout[2 * p + 1][j] = fmaxf(f.y + bb, 0.f);
            }

        if (MODE == 0) {
#pragma unroll
            for (int i = 0; i < 4; i++) {
                int d = sDst[ty * 4 + i];
                float4 v = make_float4(vout[i][0], vout[i][1], vout[i][2], vout[i][3]);
                atomicAdd(reinterpret_cast<float4*>(g_agg + d * H + tx * 4), v);
            }
        } else {
            float s[4] = {0, 0, 0, 0}, ss[4] = {0, 0, 0, 0};
#pragma unroll
            for (int i = 0; i < 4; i++) {
                int n = e0 + ty * 4 + i;
                float4 v = make_float4(vout[i][0], vout[i][1], vout[i][2], vout[i][3]);
                *reinterpret_cast<float4*>(g_u + n * H + tx * 4) = v;
                s[0] += v.x; ss[0] += v.x * v.x;
                s[1] += v.y; ss[1] += v.y * v.y;
                s[2] += v.z; ss[2] += v.z * v.z;
                s[3] += v.w; ss[3] += v.w * v.w;
            }
            __syncthreads();
            float* sRed = sA;
#pragma unroll
            for (int j = 0; j < 4; j++) {
                sRed[ty * 64 + tx * 4 + j] = s[j];
                sRed[1024 + ty * 64 + tx * 4 + j] = ss[j];
            }
            __syncthreads();
            if (tid < H) {
                float a = 0.f, b = 0.f;
#pragma unroll
                for (int r = 0; r < 16; r++) {
                    a += sRed[r * 64 + tid];
                    b += sRed[1024 + r * 64 + tid];
                }
                int bat = e0 / NS;
                atomicAdd(&g_stats[(bat * H + tid) * 2 + 0], a);
                atomicAdd(&g_stats[(bat * H + tid) * 2 + 1], b);
            }
        }
    }
}

// -------------------- InstanceNorm apply (float4) --------------------
__global__ void k_norm() {
    int idx = blockIdx.x * blockDim.x + threadIdx.x;  // NN*H/4 threads
    int n = idx >> 4;
    int c = (idx & 15) << 2;
    int b = n >> 11;
    float4 u = *(const float4*)(g_u + n * H + c);
    const float2* st = (const float2*)(g_stats + (b * H + c) * 2);
    float4 r;
    {
        float2 p = st[0];
        float mean = p.x * (1.f / NS);
        float var = p.y * (1.f / NS) - mean * mean;
        r.x = (u.x - mean) * rsqrtf(var + EPSN);
    }
    {
        float2 p = st[1];
        float mean = p.x * (1.f / NS);
        float var = p.y * (1.f / NS) - mean * mean;
        r.y = (u.y - mean) * rsqrtf(var + EPSN);
    }
    {
        float2 p = st[2];
        float mean = p.x * (1.f / NS);
        float var = p.y * (1.f / NS) - mean * mean;
        r.z = (u.z - mean) * rsqrtf(var + EPSN);
    }
    {
        float2 p = st[3];
        float mean = p.x * (1.f / NS);
        float var = p.y * (1.f / NS) - mean * mean;
        r.w = (u.w - mean) * rsqrtf(var + EPSN);
    }
    *(float4*)(g_h + n * H + c) = r;
}

// -------------------- decoder + normalize --------------------
__global__ void k_decode(const float* __restrict__ W, const float* __restrict__ b,
                         float* __restrict__ out) {
    __shared__ float sW[H * 3];
    __shared__ float sb[3];
    int tid = threadIdx.x;
    if (tid < H * 3) sW[tid] = W[tid];
    if (tid < 3) sb[tid] = b[tid];
    __syncthreads();
    int n = blockIdx.x * blockDim.x + tid;
    const float4* hr = (const float4*)(g_h + n * H);
    float a0 = sb[0], a1 = sb[1], a2 = sb[2];
#pragma unroll
    for (int k4 = 0; k4 < 16; k4++) {
        float4 v = hr[k4];
        int k = k4 * 4;
        a0 = fmaf(v.x, sW[(k + 0) * 3 + 0], a0); a1 = fmaf(v.x, sW[(k + 0) * 3 + 1], a1); a2 = fmaf(v.x, sW[(k + 0) * 3 + 2], a2);
        a0 = fmaf(v.y, sW[(k + 1) * 3 + 0], a0); a1 = fmaf(v.y, sW[(k + 1) * 3 + 1], a1); a2 = fmaf(v.y, sW[(k + 1) * 3 + 2], a2);
        a0 = fmaf(v.z, sW[(k + 2) * 3 + 0], a0); a1 = fmaf(v.z, sW[(k + 2) * 3 + 1], a1); a2 = fmaf(v.z, sW[(k + 2) * 3 + 2], a2);
        a0 = fmaf(v.w, sW[(k + 3) * 3 + 0], a0); a1 = fmaf(v.w, sW[(k + 3) * 3 + 1], a1); a2 = fmaf(v.w, sW[(k + 3) * 3 + 2], a2);
    }
    float inv = rsqrtf(a0 * a0 + a1 * a1 + a2 * a2);
    a0 *= inv; a1 *= inv; a2 *= inv;
    g_X[n * 3 + 0] = a0; g_X[n * 3 + 1] = a1; g_X[n * 3 + 2] = a2;
    out[n * 3 + 0] = a0; out[n * 3 + 1] = a1; out[n * 3 + 2] = a2;
}

// -------------------- fibonacci sphere + kYY --------------------
__global__ void k_fib_kyy() {
    __shared__ float sY[NY * 3];
    __shared__ float wsum[2];
    int i = threadIdx.x;  // 64 threads
    double phi = 3.14159265358979323846 * (3.0 - sqrt(5.0));
    double y = 1.0 - 2.0 * (double)i / 63.0;
    double r = sqrt(fmax(0.0, 1.0 - y * y));
    double th = phi * (double)i;
    float Yx = (float)(cos(th) * r), Yy = (float)y, Yz = (float)(sin(th) * r);
    sY[i * 3 + 0] = Yx; sY[i * 3 + 1] = Yy; sY[i * 3 + 2] = Yz;
    g_Y[i * 3 + 0] = Yx; g_Y[i * 3 + 1] = Yy; g_Y[i * 3 + 2] = Yz;
    __syncthreads();
    float acc = 0.f;
    for (int j = 0; j < NY; j++) {
        float d = Yx * sY[j * 3] + Yy * sY[j * 3 + 1] + Yz * sY[j * 3 + 2];
        acc += __expf(fmaf(2.f, d, -2.f));
    }
    for (int o = 16; o > 0; o >>= 1) acc += __shfl_down_sync(0xffffffffu, acc, o);
    if ((i & 31) == 0) wsum[i >> 5] = acc;
    __syncthreads();
    if (i == 0) g_acc[2] = ((double)wsum[0] + (double)wsum[1]) / (64.0 * 64.0);
}

// -------------------- kXY --------------------
__global__ void k_kxy() {
    __shared__ float sY[NY * 3];
    int tid = threadIdx.x;
    if (tid < NY * 3) sY[tid] = g_Y[tid];
    __syncthreads();
    int n = blockIdx.x * blockDim.x + tid;
    float x0 = g_X[n * 3], x1 = g_X[n * 3 + 1], x2 = g_X[n * 3 + 2];
    float acc = 0.f;
#pragma unroll 4
    for (int j = 0; j < NY; j++) {
        float d = fmaf(x0, sY[j * 3], fmaf(x1, sY[j * 3 + 1], x2 * sY[j * 3 + 2]));
        acc += __expf(fmaf(2.f, d, -2.f));
    }
    for (int o = 16; o > 0; o >>= 1) acc += __shfl_down_sync(0xffffffffu, acc, o);
    if ((tid & 31) == 0) atomicAdd(&g_acc[1], (double)acc);
}

// -------------------- kXX --------------------
__global__ void __launch_bounds__(128) k_kxx() {
    __shared__ float sx[NS], sy[NS], sz[NS];
    int b = blockIdx.x, tid = threadIdx.x;
    const float* Xb = g_X + b * NS * 3;
    for (int t = tid; t < NS; t += 128) {
        sx[t] = Xb[t * 3]; sy[t] = Xb[t * 3 + 1]; sz[t] = Xb[t * 3 + 2];
    }
    __syncthreads();
    int row = blockIdx.y * 128 + tid;
    float x0 = sx[row], x1 = sy[row], x2 = sz[row];
    float acc = 0.f;
#pragma unroll 4
    for (int j = 0; j < NS; j++) {
        float d = fmaf(x0, sx[j], fmaf(x1, sy[j], x2 * sz[j]));
        acc += __expf(fmaf(2.f, d, -2.f));
    }
    for (int o = 16; o > 0; o >>= 1) acc += __shfl_down_sync(0xffffffffu, acc, o);
    if ((tid & 31) == 0) atomicAdd(&g_acc[0], (double)acc);
}

// -------------------- finalize loss --------------------
__global__ void k_final(float* out, int writeLoss) {
    double loss = g_acc[0] / ((double)NBATCH * NS * NS)
                - 2.0 * g_acc[1] / ((double)NBATCH * NS * NY)
                + g_acc[2];
    if (writeLoss) out[0] = (float)loss;
}

// -------------------- host launch --------------------
extern "C" void kernel_launch(void* const* d_in, const int* in_sizes, int n_in,
                              void* d_out, int out_size) {
    const float* x    = (const float*)d_in[0];
    const int*   esrc = (const int*)d_in[1];
    const int*   edst = (const int*)d_in[2];
    int o = (in_sizes[3] == 1) ? 4 : 3;
    const float* encW = (const float*)d_in[o + 0];
    const float* encb = (const float*)d_in[o + 1];
    const float* m1W  = (const float*)d_in[o + 2];
    const float* m1b  = (const float*)d_in[o + 3];
    const float* m2W  = (const float*)d_in[o + 4];
    const float* m2b  = (const float*)d_in[o + 5];
    const float* u1W  = (const float*)d_in[o + 6];
    const float* u1b  = (const float*)d_in[o + 7];
    const float* u2W  = (const float*)d_in[o + 8];
    const float* u2b  = (const float*)d_in[o + 9];
    const float* decW = (const float*)d_in[o + 10];
    const float* decb = (const float*)d_in[o + 11];
    float* out = (float*)d_out;
    int base = (out_size >= NN * 3 + 1) ? 1 : 0;

    size_t SMEM = (size_t)(H2 * H + H * H + H2 * TEP + H * TEP) * sizeof(float)
                + TE * sizeof(int);
    cudaFuncSetAttribute(k_mlp<0>, cudaFuncAttributeMaxDynamicSharedMemorySize, (int)SMEM);
    cudaFuncSetAttribute(k_mlp<1>, cudaFuncAttributeMaxDynamicSharedMemorySize, (int)SMEM);

    void *p_agg, *p_stats, *p_acc;
    cudaGetSymbolAddress(&p_agg, g_agg);
    cudaGetSymbolAddress(&p_stats, g_stats);
    cudaGetSymbolAddress(&p_acc, g_acc);

    k_encode<<<NN * H / 256, 256>>>(x, encW, encb);

    for (int l = 0; l < NL; l++) {
        cudaMemsetAsync(p_agg, 0, (size_t)NN * H * sizeof(float));
        k_mlp<0><<<GRID_MLP, 256, SMEM>>>(esrc, edst,
                                          m1W + l * H2 * H, m1b + l * H,
                                          m2W + l * H * H, m2b + l * H);
        cudaMemsetAsync(p_stats, 0, (size_t)NBATCH * H * 2 * sizeof(float));
        k_mlp<1><<<GRID_MLP, 256, SMEM>>>(nullptr, nullptr,
                                          u1W + l * H2 * H, u1b + l * H,
                                          u2W + l * H * H, u2b + l * H);
        k_norm<<<NN * H / 4 / 256, 256>>>();
    }

    k_decode<<<NN / 256, 256>>>(decW, decb, out + base);

    cudaMemsetAsync(p_acc, 0, 3 * sizeof(double));
    k_fib_kyy<<<1, 64>>>();
    k_kxy<<<NN / 256, 256>>>();
    dim3 gxx(NBATCH, NS / 128);
    k_kxx<<<gxx, 128>>>();
    k_final<<<1, 1>>>(out, base);
}

// round 8
// speedup vs baseline: 1.6522x; 1.6522x over previous
#include <cuda_runtime.h>
#include <math.h>
#include <cstdint>

#define NN 32768
#define NE 524288
#define H 64
#define H2 128
#define NBATCH 16
#define NS 2048
#define NL 4
#define NY 64
#define EPSN 1e-5f
#define TE 64
#define TEP 68
#define GRID_NODE 296
#define GRID_EDGE 148
#define NG (NE / 16)

typedef unsigned long long u64;

__device__ float g_h[NN * H];
__device__ float g_agg[NN * H];
__device__ float g_u[NN * H];
__device__ float g_stats[NBATCH * H * 2];
__device__ float g_X[NN * 3];
__device__ float g_Y[NY * 3];
__device__ double g_acc[3];

// ---------- helpers ----------
__device__ __forceinline__ uint32_t smem_u32(const void* p) {
    uint32_t a;
    asm("{ .reg .u64 t; cvta.to.shared.u64 t, %1; cvt.u32.u64 %0, t; }" : "=r"(a) : "l"(p));
    return a;
}
__device__ __forceinline__ uint32_t pack2bf(float f0, float f1) {
    uint32_t r;  // lo half = f0, hi half = f1
    asm("cvt.rn.satfinite.bf16x2.f32 %0, %1, %2;" : "=r"(r) : "f"(f1), "f"(f0));
    return r;
}
__device__ __forceinline__ float bflo(uint32_t h) { return __uint_as_float(h << 16); }
__device__ __forceinline__ float bfhi(uint32_t h) { return __uint_as_float(h & 0xFFFF0000u); }
__device__ __forceinline__ void split2(float f0, float f1, uint32_t& hp, uint32_t& lp) {
    hp = pack2bf(f0, f1);
    lp = pack2bf(f0 - bflo(hp), f1 - bfhi(hp));
}
__device__ __forceinline__ void ldsm4(uint32_t* r, uint32_t addr) {
    asm volatile("ldmatrix.sync.aligned.m8n8.x4.shared.b16 {%0,%1,%2,%3}, [%4];"
        : "=r"(r[0]), "=r"(r[1]), "=r"(r[2]), "=r"(r[3]) : "r"(addr));
}
__device__ __forceinline__ void mma_bf16(float* c, const uint32_t* a, uint32_t b0, uint32_t b1) {
    asm("mma.sync.aligned.m16n8k16.row.col.f32.bf16.bf16.f32 "
        "{%0,%1,%2,%3}, {%4,%5,%6,%7}, {%8,%9}, {%0,%1,%2,%3};"
        : "+f"(c[0]), "+f"(c[1]), "+f"(c[2]), "+f"(c[3])
        : "r"(a[0]), "r"(a[1]), "r"(a[2]), "r"(a[3]), "r"(b0), "r"(b1));
}

// smem byte offsets (edge kernel). Rows padded to 272B (W1/A1: 128k+8 bf16) /
// 144B (W2/A2: 64k+8 bf16) so ldmatrix row addresses land on distinct banks.
#define OFF_W1HI 0
#define OFF_W1LO 17408
#define OFF_W2HI 34816
#define OFF_W2LO 44032
#define OFF_B1   53248
#define OFF_B2   53504
#define OFF_A1HI 53760
#define OFF_A1LO 88576
#define OFF_A2HI 123392
#define OFF_A2LO 141824
#define OFF_DST  160256
#define SMEM_EDGE 160768

// ======== edge MLP on HMMA (mma.sync bf16, 2-term split) ========
// Each warp owns 16 edges end-to-end; no block syncs in the mainloop.
__global__ void __launch_bounds__(256, 1)
k_edge_tc(const int* __restrict__ esrc, const int* __restrict__ edst,
          const float* __restrict__ W1, const float* __restrict__ b1,
          const float* __restrict__ W2, const float* __restrict__ b2) {
    extern __shared__ char sm[];
    const uint32_t sb = smem_u32(sm);
    const int tid = threadIdx.x;
    const int wid = tid >> 5, lane = tid & 31;

    // ---- stage weights once per CTA: [n][k] bf16 hi/lo, padded rows ----
    {
        int n = tid >> 2, kq = tid & 3;
#pragma unroll
        for (int p = 0; p < 16; ++p) {
            int k = kq * 32 + 2 * p;
            uint32_t hp, lp;
            split2(W1[k * H + n], W1[(k + 1) * H + n], hp, lp);
            *(uint32_t*)(sm + OFF_W1HI + n * 272 + k * 2) = hp;
            *(uint32_t*)(sm + OFF_W1LO + n * 272 + k * 2) = lp;
        }
#pragma unroll
        for (int p = 0; p < 8; ++p) {
            int k = kq * 16 + 2 * p;
            uint32_t hp, lp;
            split2(W2[k * H + n], W2[(k + 1) * H + n], hp, lp);
            *(uint32_t*)(sm + OFF_W2HI + n * 144 + k * 2) = hp;
            *(uint32_t*)(sm + OFF_W2LO + n * 144 + k * 2) = lp;
        }
        if (tid < H) {
            *(float*)(sm + OFF_B1 + tid * 4) = b1[tid];
            *(float*)(sm + OFF_B2 + tid * 4) = b2[tid];
        }
    }
    __syncthreads();

    const int R = wid * 16;
    const int quad = lane >> 3, r8 = lane & 7;
    // ldmatrix lane geometry: A x4 = (R,k0)(R+8,k0)(R,k8)(R+8,k8); B x4 = 2 n-tiles
    const int a_row = R + r8 + (quad & 1) * 8;
    const int a_k8 = (quad >> 1) * 8;
    const int b_nr = r8 + (quad >> 1) * 8;
    const int b_k8 = (quad & 1) * 8;

    const uint32_t a1hiA = sb + OFF_A1HI + a_row * 272 + a_k8 * 2;
    const uint32_t a1loA = sb + OFF_A1LO + a_row * 272 + a_k8 * 2;
    const uint32_t a2hiA = sb + OFF_A2HI + a_row * 144 + a_k8 * 2;
    const uint32_t a2loA = sb + OFF_A2LO + a_row * 144 + a_k8 * 2;
    uint32_t w1hiA[4], w1loA[4], w2hiA[4], w2loA[4];
#pragma unroll
    for (int pi = 0; pi < 4; ++pi) {
        w1hiA[pi] = sb + OFF_W1HI + (pi * 16 + b_nr) * 272 + b_k8 * 2;
        w1loA[pi] = sb + OFF_W1LO + (pi * 16 + b_nr) * 272 + b_k8 * 2;
        w2hiA[pi] = sb + OFF_W2HI + (pi * 16 + b_nr) * 144 + b_k8 * 2;
        w2loA[pi] = sb + OFF_W2LO + (pi * 16 + b_nr) * 144 + b_k8 * 2;
    }

    const float* sB1 = (const float*)(sm + OFF_B1);
    const float* sB2 = (const float*)(sm + OFF_B2);
    int* sDst = (int*)(sm + OFF_DST);

    const int erow0 = R + (lane >> 2);   // D-frag rows erow0, erow0+8
    const int ec = (lane & 3) * 2;       // D-frag col pair base
    const int srow = lane >> 1, shalf = lane & 1;   // staging: 2 lanes per edge

    char* stHi = sm + OFF_A1HI + (R + srow) * 272 + shalf * 128;
    char* stLo = sm + OFF_A1LO + (R + srow) * 272 + shalf * 128;
    char* e2hi = sm + OFF_A2HI + erow0 * 144;
    char* e2lo = sm + OFF_A2LO + erow0 * 144;
    char* so0 = sm + OFF_A1HI + erow0 * 272;          // f32 out bounce (reuses A1hi)
    const char* sor = sm + OFF_A1HI + (R + srow) * 272;

    for (int g = blockIdx.x * 8 + wid; g < NG; g += gridDim.x * 8) {
        __syncwarp();
        // ---- gather + split 16 edges: A1 = [h[dst] ; h[src]] ----
        {
            int e = g * 16 + srow;
            int nd = edst[e];
            if (shalf == 0) sDst[R + srow] = nd;
            int node = shalf ? esrc[e] : nd;
            const float4* p = (const float4*)(g_h + node * H);
#pragma unroll
            for (int q = 0; q < 8; ++q) {
                float4 v0 = p[2 * q], v1 = p[2 * q + 1];
                uint32_t h0, h1, h2, h3, l0, l1, l2, l3;
                split2(v0.x, v0.y, h0, l0);
                split2(v0.z, v0.w, h1, l1);
                split2(v1.x, v1.y, h2, l2);
                split2(v1.z, v1.w, h3, l3);
                *(uint4*)(stHi + q * 16) = make_uint4(h0, h1, h2, h3);
                *(uint4*)(stLo + q * 16) = make_uint4(l0, l1, l2, l3);
            }
        }
        __syncwarp();

        // ---- GEMM1: [16,128] @ W1^T[128,64], 3-pass split ----
        float acc[8][4];
#pragma unroll
        for (int nt = 0; nt < 8; ++nt)
            acc[nt][0] = acc[nt][1] = acc[nt][2] = acc[nt][3] = 0.f;
#pragma unroll
        for (int kt = 0; kt < 8; ++kt) {
            uint32_t ah[4], al[4];
            ldsm4(ah, a1hiA + kt * 32);
            ldsm4(al, a1loA + kt * 32);
#pragma unroll
            for (int pi = 0; pi < 4; ++pi) {
                uint32_t bh[4], bl[4];
                ldsm4(bh, w1hiA[pi] + kt * 32);
                ldsm4(bl, w1loA[pi] + kt * 32);
                mma_bf16(acc[2 * pi], ah, bh[0], bh[1]);
                mma_bf16(acc[2 * pi], ah, bl[0], bl[1]);
                mma_bf16(acc[2 * pi], al, bh[0], bh[1]);
                mma_bf16(acc[2 * pi + 1], ah, bh[2], bh[3]);
                mma_bf16(acc[2 * pi + 1], ah, bl[2], bl[3]);
                mma_bf16(acc[2 * pi + 1], al, bh[2], bh[3]);
            }
        }

        // ---- epi1: bias+relu -> split -> A2 ----
#pragma unroll
        for (int nt = 0; nt < 8; ++nt) {
            int col = nt * 8 + ec;
            float bb0 = sB1[col], bb1 = sB1[col + 1];
            uint32_t hp, lp;
            split2(fmaxf(acc[nt][0] + bb0, 0.f), fmaxf(acc[nt][1] + bb1, 0.f), hp, lp);
            *(uint32_t*)(e2hi + col * 2) = hp;
            *(uint32_t*)(e2lo + col * 2) = lp;
            split2(fmaxf(acc[nt][2] + bb0, 0.f), fmaxf(acc[nt][3] + bb1, 0.f), hp, lp);
            *(uint32_t*)(e2hi + 8 * 144 + col * 2) = hp;
            *(uint32_t*)(e2lo + 8 * 144 + col * 2) = lp;
        }
        __syncwarp();

        // ---- GEMM2: [16,64] @ W2^T[64,64] ----
        float acc2[8][4];
#pragma unroll
        for (int nt = 0; nt < 8; ++nt)
            acc2[nt][0] = acc2[nt][1] = acc2[nt][2] = acc2[nt][3] = 0.f;
#pragma unroll
        for (int kt = 0; kt < 4; ++kt) {
            uint32_t ah[4], al[4];
            ldsm4(ah, a2hiA + kt * 32);
            ldsm4(al, a2loA + kt * 32);
#pragma unroll
            for (int pi = 0; pi < 4; ++pi) {
                uint32_t bh[4], bl[4];
                ldsm4(bh, w2hiA[pi] + kt * 32);
                ldsm4(bl, w2loA[pi] + kt * 32);
                mma_bf16(acc2[2 * pi], ah, bh[0], bh[1]);
                mma_bf16(acc2[2 * pi], ah, bl[0], bl[1]);
                mma_bf16(acc2[2 * pi], al, bh[0], bh[1]);
                mma_bf16(acc2[2 * pi + 1], ah, bh[2], bh[3]);
                mma_bf16(acc2[2 * pi + 1], ah, bl[2], bl[3]);
                mma_bf16(acc2[2 * pi + 1], al, bh[2], bh[3]);
            }
        }

        // ---- epi2: bias+relu -> f32 bounce -> float4 atomic scatter ----
#pragma unroll
        for (int nt = 0; nt < 8; ++nt) {
            int col = nt * 8 + ec;
            float bb0 = sB2[col], bb1 = sB2[col + 1];
            *(float2*)(so0 + col * 4) =
                make_float2(fmaxf(acc2[nt][0] + bb0, 0.f), fmaxf(acc2[nt][1] + bb1, 0.f));
            *(float2*)(so0 + 8 * 272 + col * 4) =
                make_float2(fmaxf(acc2[nt][2] + bb0, 0.f), fmaxf(acc2[nt][3] + bb1, 0.f));
        }
        __syncwarp();
        {
            int dn = sDst[R + srow];
            float* dst = g_agg + dn * H + shalf * 32;
#pragma unroll
            for (int i = 0; i < 8; ++i) {
                float4 v = *(const float4*)(sor + (shalf * 32 + i * 4) * 4);
                atomicAdd((float4*)(dst + i * 4), v);
            }
        }
    }
}

// ======== FFMA2 helpers / node MLP (validated path) ========
__device__ __forceinline__ u64 fma2(u64 a, u64 b, u64 c) {
    u64 d; asm("fma.rn.f32x2 %0, %1, %2, %3;" : "=l"(d) : "l"(a), "l"(b), "l"(c)); return d;
}
__device__ __forceinline__ u64 dup2(float w) {
    u64 d; asm("mov.b64 %0, {%1, %1};" : "=l"(d) : "f"(w)); return d;
}
__device__ __forceinline__ float2 unpack2(u64 u) {
    float2 f; asm("mov.b64 {%0, %1}, %2;" : "=f"(f.x), "=f"(f.y) : "l"(u)); return f;
}

__global__ void k_encode(const float* __restrict__ x, const float* __restrict__ W,
                         const float* __restrict__ b) {
    int idx = blockIdx.x * blockDim.x + threadIdx.x;
    int n = idx >> 6, c = idx & 63;
    float x0 = x[n * 3 + 0], x1 = x[n * 3 + 1], x2 = x[n * 3 + 2];
    g_h[idx] = fmaf(x0, W[c], fmaf(x1, W[H + c], fmaf(x2, W[2 * H + c], b[c])));
}

__global__ void __launch_bounds__(256, 2)
k_node(const float* __restrict__ W1, const float* __restrict__ b1,
       const float* __restrict__ W2, const float* __restrict__ b2) {
    extern __shared__ float smf[];
    float* sW1 = smf;
    float* sW2 = sW1 + H2 * H;
    float* sA = sW2 + H * H;
    float* sT = sA + H2 * TEP;

    const int tid = threadIdx.x;
    const int tx = tid & 15, ty = tid >> 4;
    {
        const float4* g1 = (const float4*)W1; float4* d1 = (float4*)sW1;
#pragma unroll
        for (int t = 0; t < 8; ++t) d1[tid + t * 256] = g1[tid + t * 256];
        const float4* g2 = (const float4*)W2; float4* d2 = (float4*)sW2;
#pragma unroll
        for (int t = 0; t < 4; ++t) d2[tid + t * 256] = g2[tid + t * 256];
    }
    float bia1[4], bia2[4];
#pragma unroll
    for (int j = 0; j < 4; j++) { bia1[j] = b1[tx * 4 + j]; bia2[j] = b2[tx * 4 + j]; }

    for (int tile = blockIdx.x; tile < NN / TE; tile += gridDim.x) {
        const int e0 = tile * TE;
        __syncthreads();
        {
            int e = tid >> 2, p = tid & 3;
            int n = e0 + e;
            const float4* r0 = (const float4*)(g_h + n * H);
            const float4* r1 = (const float4*)(g_agg + n * H);
#pragma unroll
            for (int q = 0; q < 4; ++q) {
                float4 v = r0[p * 4 + q];
                int k = p * 16 + q * 4;
                sA[(k + 0) * TEP + e] = v.x; sA[(k + 1) * TEP + e] = v.y;
                sA[(k + 2) * TEP + e] = v.z; sA[(k + 3) * TEP + e] = v.w;
                float4 w = r1[p * 4 + q];
                sA[(k + 64) * TEP + e] = w.x; sA[(k + 65) * TEP + e] = w.y;
                sA[(k + 66) * TEP + e] = w.z; sA[(k + 67) * TEP + e] = w.w;
            }
        }
        __syncthreads();

        u64 acc[2][4];
#pragma unroll
        for (int p = 0; p < 2; p++)
#pragma unroll
            for (int j = 0; j < 4; j++) acc[p][j] = 0ull;
#pragma unroll 8
        for (int k = 0; k < H2; ++k) {
            const u64* ap = (const u64*)(sA + k * TEP + ty * 4);
            u64 a01 = ap[0], a23 = ap[1];
            float4 w4 = *(const float4*)(sW1 + k * H + tx * 4);
            u64 w0 = dup2(w4.x), w1 = dup2(w4.y), w2 = dup2(w4.z), w3 = dup2(w4.w);
            acc[0][0] = fma2(a01, w0, acc[0][0]); acc[1][0] = fma2(a23, w0, acc[1][0]);
            acc[0][1] = fma2(a01, w1, acc[0][1]); acc[1][1] = fma2(a23, w1, acc[1][1]);
            acc[0][2] = fma2(a01, w2, acc[0][2]); acc[1][2] = fma2(a23, w2, acc[1][2]);
            acc[0][3] = fma2(a01, w3, acc[0][3]); acc[1][3] = fma2(a23, w3, acc[1][3]);
        }
#pragma unroll
        for (int j = 0; j < 4; j++) {
            float bb = bia1[j];
            float2 f0 = unpack2(acc[0][j]);
            float2 f1 = unpack2(acc[1][j]);
            float* dst = sT + (tx * 4 + j) * TEP + ty * 4;
            *(float2*)(dst) = make_float2(fmaxf(f0.x + bb, 0.f), fmaxf(f0.y + bb, 0.f));
            *(float2*)(dst + 2) = make_float2(fmaxf(f1.x + bb, 0.f), fmaxf(f1.y + bb, 0.f));
        }
        __syncthreads();

        u64 acc2[2][4];
#pragma unroll
        for (int p = 0; p < 2; p++)
#pragma unroll
            for (int j = 0; j < 4; j++) acc2[p][j] = 0ull;
#pragma unroll 8
        for (int k = 0; k < H; ++k) {
            const u64* ap = (const u64*)(sT + k * TEP + ty * 4);
            u64 a01 = ap[0], a23 = ap[1];
            float4 w4 = *(const float4*)(sW2 + k * H + tx * 4);
            u64 w0 = dup2(w4.x), w1 = dup2(w4.y), w2 = dup2(w4.z), w3 = dup2(w4.w);
            acc2[0][0] = fma2(a01, w0, acc2[0][0]); acc2[1][0] = fma2(a23, w0, acc2[1][0]);
            acc2[0][1] = fma2(a01, w1, acc2[0][1]); acc2[1][1] = fma2(a23, w1, acc2[1][1]);
            acc2[0][2] = fma2(a01, w2, acc2[0][2]); acc2[1][2] = fma2(a23, w2, acc2[1][2]);
            acc2[0][3] = fma2(a01, w3, acc2[0][3]); acc2[1][3] = fma2(a23, w3, acc2[1][3]);
        }
        float vout[4][4];
#pragma unroll
        for (int p = 0; p < 2; p++)
#pragma unroll
            for (int j = 0; j < 4; j++) {
                float bb = bia2[j];
                float2 f = unpack2(acc2[p][j]);
                vout[2 * p + 0][j] = fmaxf(f.x + bb, 0.f);
                vout[2 * p + 1][j] = fmaxf(f.y + bb, 0.f);
            }
        float s[4] = {0, 0, 0, 0}, ss[4] = {0, 0, 0, 0};
#pragma unroll
        for (int i = 0; i < 4; i++) {
            int n = e0 + ty * 4 + i;
            float4 v = make_float4(vout[i][0], vout[i][1], vout[i][2], vout[i][3]);
            *reinterpret_cast<float4*>(g_u + n * H + tx * 4) = v;
            s[0] += v.x; ss[0] += v.x * v.x;
            s[1] += v.y; ss[1] += v.y * v.y;
            s[2] += v.z; ss[2] += v.z * v.z;
            s[3] += v.w; ss[3] += v.w * v.w;
        }
        __syncthreads();
        float* sRed = sA;
#pragma unroll
        for (int j = 0; j < 4; j++) {
            sRed[ty * 64 + tx * 4 + j] = s[j];
            sRed[1024 + ty * 64 + tx * 4 + j] = ss[j];
        }
        __syncthreads();
        if (tid < H) {
            float a = 0.f, b = 0.f;
#pragma unroll
            for (int r = 0; r < 16; r++) {
                a += sRed[r * 64 + tid];
                b += sRed[1024 + r * 64 + tid];
            }
            int bat = e0 / NS;
            atomicAdd(&g_stats[(bat * H + tid) * 2 + 0], a);
            atomicAdd(&g_stats[(bat * H + tid) * 2 + 1], b);
        }
    }
}

__global__ void k_norm() {
    int idx = blockIdx.x * blockDim.x + threadIdx.x;
    int n = idx >> 4;
    int c = (idx & 15) << 2;
    int b = n >> 11;
    float4 u = *(const float4*)(g_u + n * H + c);
    const float2* st = (const float2*)(g_stats + (b * H + c) * 2);
    float4 r;
    { float2 p = st[0]; float m = p.x * (1.f / NS), v = p.y * (1.f / NS) - m * m; r.x = (u.x - m) * rsqrtf(v + EPSN); }
    { float2 p = st[1]; float m = p.x * (1.f / NS), v = p.y * (1.f / NS) - m * m; r.y = (u.y - m) * rsqrtf(v + EPSN); }
    { float2 p = st[2]; float m = p.x * (1.f / NS), v = p.y * (1.f / NS) - m * m; r.z = (u.z - m) * rsqrtf(v + EPSN); }
    { float2 p = st[3]; float m = p.x * (1.f / NS), v = p.y * (1.f / NS) - m * m; r.w = (u.w - m) * rsqrtf(v + EPSN); }
    *(float4*)(g_h + n * H + c) = r;
}

__global__ void k_decode(const float* __restrict__ W, const float* __restrict__ b,
                         float* __restrict__ out) {
    __shared__ float sW[H * 3];
    __shared__ float sbv[3];
    int tid = threadIdx.x;
    if (tid < H * 3) sW[tid] = W[tid];
    if (tid < 3) sbv[tid] = b[tid];
    __syncthreads();
    int n = blockIdx.x * blockDim.x + tid;
    const float4* hr = (const float4*)(g_h + n * H);
    float a0 = sbv[0], a1 = sbv[1], a2 = sbv[2];
#pragma unroll
    for (int k4 = 0; k4 < 16; k4++) {
        float4 v = hr[k4];
        int k = k4 * 4;
        a0 = fmaf(v.x, sW[(k + 0) * 3 + 0], a0); a1 = fmaf(v.x, sW[(k + 0) * 3 + 1], a1); a2 = fmaf(v.x, sW[(k + 0) * 3 + 2], a2);
        a0 = fmaf(v.y, sW[(k + 1) * 3 + 0], a0); a1 = fmaf(v.y, sW[(k + 1) * 3 + 1], a1); a2 = fmaf(v.y, sW[(k + 1) * 3 + 2], a2);
        a0 = fmaf(v.z, sW[(k + 2) * 3 + 0], a0); a1 = fmaf(v.z, sW[(k + 2) * 3 + 1], a1); a2 = fmaf(v.z, sW[(k + 2) * 3 + 2], a2);
        a0 = fmaf(v.w, sW[(k + 3) * 3 + 0], a0); a1 = fmaf(v.w, sW[(k + 3) * 3 + 1], a1); a2 = fmaf(v.w, sW[(k + 3) * 3 + 2], a2);
    }
    float inv = rsqrtf(a0 * a0 + a1 * a1 + a2 * a2);
    a0 *= inv; a1 *= inv; a2 *= inv;
    g_X[n * 3 + 0] = a0; g_X[n * 3 + 1] = a1; g_X[n * 3 + 2] = a2;
    out[n * 3 + 0] = a0; out[n * 3 + 1] = a1; out[n * 3 + 2] = a2;
}

__global__ void k_fib_kyy() {
    __shared__ float sY[NY * 3];
    __shared__ float wsum[2];
    int i = threadIdx.x;
    double phi = 3.14159265358979323846 * (3.0 - sqrt(5.0));
    double y = 1.0 - 2.0 * (double)i / 63.0;
    double r = sqrt(fmax(0.0, 1.0 - y * y));
    double th = phi * (double)i;
    float Yx = (float)(cos(th) * r), Yy = (float)y, Yz = (float)(sin(th) * r);
    sY[i * 3 + 0] = Yx; sY[i * 3 + 1] = Yy; sY[i * 3 + 2] = Yz;
    g_Y[i * 3 + 0] = Yx; g_Y[i * 3 + 1] = Yy; g_Y[i * 3 + 2] = Yz;
    __syncthreads();
    float acc = 0.f;
    for (int j = 0; j < NY; j++) {
        float d = Yx * sY[j * 3] + Yy * sY[j * 3 + 1] + Yz * sY[j * 3 + 2];
        acc += __expf(fmaf(2.f, d, -2.f));
    }
    for (int o = 16; o > 0; o >>= 1) acc += __shfl_down_sync(0xffffffffu, acc, o);
    if ((i & 31) == 0) wsum[i >> 5] = acc;
    __syncthreads();
    if (i == 0) g_acc[2] = ((double)wsum[0] + (double)wsum[1]) / (64.0 * 64.0);
}

__global__ void k_kxy() {
    __shared__ float sY[NY * 3];
    int tid = threadIdx.x;
    if (tid < NY * 3) sY[tid] = g_Y[tid];
    __syncthreads();
    int n = blockIdx.x * blockDim.x + tid;
    float x0 = g_X[n * 3], x1 = g_X[n * 3 + 1], x2 = g_X[n * 3 + 2];
    float acc = 0.f;
#pragma unroll 4
    for (int j = 0; j < NY; j++) {
        float d = fmaf(x0, sY[j * 3], fmaf(x1, sY[j * 3 + 1], x2 * sY[j * 3 + 2]));
        acc += __expf(fmaf(2.f, d, -2.f));
    }
    for (int o = 16; o > 0; o >>= 1) acc += __shfl_down_sync(0xffffffffu, acc, o);
    if ((tid & 31) == 0) atomicAdd(&g_acc[1], (double)acc);
}

__global__ void __launch_bounds__(128) k_kxx() {
    __shared__ float sx[NS], sy[NS], sz[NS];
    int b = blockIdx.x, tid = threadIdx.x;
    const float* Xb = g_X + b * NS * 3;
    for (int t = tid; t < NS; t += 128) {
        sx[t] = Xb[t * 3]; sy[t] = Xb[t * 3 + 1]; sz[t] = Xb[t * 3 + 2];
    }
    __syncthreads();
    int row = blockIdx.y * 128 + tid;
    float x0 = sx[row], x1 = sy[row], x2 = sz[row];
    float acc = 0.f;
#pragma unroll 4
    for (int j = 0; j < NS; j++) {
        float d = fmaf(x0, sx[j], fmaf(x1, sy[j], x2 * sz[j]));
        acc += __expf(fmaf(2.f, d, -2.f));
    }
    for (int o = 16; o > 0; o >>= 1) acc += __shfl_down_sync(0xffffffffu, acc, o);
    if ((tid & 31) == 0) atomicAdd(&g_acc[0], (double)acc);
}

__global__ void k_final(float* out, int writeLoss) {
    double loss = g_acc[0] / ((double)NBATCH * NS * NS)
                - 2.0 * g_acc[1] / ((double)NBATCH * NS * NY)
                + g_acc[2];
    if (writeLoss) out[0] = (float)loss;
}

extern "C" void kernel_launch(void* const* d_in, const int* in_sizes, int n_in,
                              void* d_out, int out_size) {
    const float* x    = (const float*)d_in[0];
    const int*   esrc = (const int*)d_in[1];
    const int*   edst = (const int*)d_in[2];
    int o = (in_sizes[3] == 1) ? 4 : 3;
    const float* encW = (const float*)d_in[o + 0];
    const float* encb = (const float*)d_in[o + 1];
    const float* m1W  = (const float*)d_in[o + 2];
    const float* m1b  = (const float*)d_in[o + 3];
    const float* m2W  = (const float*)d_in[o + 4];
    const float* m2b  = (const float*)d_in[o + 5];
    const float* u1W  = (const float*)d_in[o + 6];
    const float* u1b  = (const float*)d_in[o + 7];
    const float* u2W  = (const float*)d_in[o + 8];
    const float* u2b  = (const float*)d_in[o + 9];
    const float* decW = (const float*)d_in[o + 10];
    const float* decb = (const float*)d_in[o + 11];
    float* out = (float*)d_out;
    int base = (out_size >= NN * 3 + 1) ? 1 : 0;

    size_t SMEM_N = (size_t)(H2 * H + H * H + H2 * TEP + H * TEP) * sizeof(float);
    cudaFuncSetAttribute(k_node, cudaFuncAttributeMaxDynamicSharedMemorySize, (int)SMEM_N);
    cudaFuncSetAttribute(k_edge_tc, cudaFuncAttributeMaxDynamicSharedMemorySize, SMEM_EDGE);

    void *p_agg, *p_stats, *p_acc;
    cudaGetSymbolAddress(&p_agg, g_agg);
    cudaGetSymbolAddress(&p_stats, g_stats);
    cudaGetSymbolAddress(&p_acc, g_acc);

    k_encode<<<NN * H / 256, 256>>>(x, encW, encb);

    for (int l = 0; l < NL; l++) {
        cudaMemsetAsync(p_agg, 0, (size_t)NN * H * sizeof(float));
        k_edge_tc<<<GRID_EDGE, 256, SMEM_EDGE>>>(esrc, edst,
                                                 m1W + l * H2 * H, m1b + l * H,
                                                 m2W + l * H * H, m2b + l * H);
        cudaMemsetAsync(p_stats, 0, (size_t)NBATCH * H * 2 * sizeof(float));
        k_node<<<GRID_NODE, 256, SMEM_N>>>(u1W + l * H2 * H, u1b + l * H,
                                           u2W + l * H * H, u2b + l * H);
        k_norm<<<NN * H / 4 / 256, 256>>>();
    }

    k_decode<<<NN / 256, 256>>>(decW, decb, out + base);

    cudaMemsetAsync(p_acc, 0, 3 * sizeof(double));
    k_fib_kyy<<<1, 64>>>();
    k_kxy<<<NN / 256, 256>>>();
    dim3 gxx(NBATCH, NS / 128);
    k_kxx<<<gxx, 128>>>();
    k_final<<<1, 1>>>(out, base);
}